// round 2
// baseline (speedup 1.0000x reference)
#include <cuda_runtime.h>
#include <math.h>

// Problem constants (fixed by reference setup_inputs)
#define NROWS 8192
#define DDIM  128
#define BT    64          // tile edge (i and j)
#define SMSTR 68          // smem row stride in floats (16B-aligned, bank-rotating)

// ---------------- scratch (no allocation allowed -> __device__ globals) ----
__device__ float g_eT[DDIM * NROWS];   // normalized embeddings, TRANSPOSED [d][i]  (4 MB)
__device__ float g_denom[NROWS];       // sum_{j!=i} exp(sim_ij)
__device__ float g_M[2][DDIM];         // per-class sums of normalized rows
__device__ int   g_cnt[2];             // class counts
__device__ float g_acc[2];             // per-class loss accumulators
__device__ int   g_lblstride;          // 1 if labels are int32, 2 if int64 (LE low word)
__device__ int   g_oddnz;              // scratch for detection

// ---------------- K_detect: label dtype sniffing ---------------------------
// Labels are 0/1. If the buffer is int64 (little-endian), the int32 view is
// [v0,0,v1,0,...]: every odd word is 0. Genuine int32 0/1 labels have random
// odd words (P(all zero) ~ 2^-4096). Only reads 8192 int32 = the minimum
// buffer size under either dtype.
__global__ void k_detect_pre() { g_oddnz = 0; }
__global__ void k_detect(const int* __restrict__ l32) {
    int t = blockIdx.x * blockDim.x + threadIdx.x;   // 0..4095
    if (l32[2 * t + 1] != 0) atomicOr(&g_oddnz, 1);
}
__global__ void k_detect_post() { g_lblstride = g_oddnz ? 1 : 2; }

__device__ __forceinline__ int get_label(const int* l32, int i) {
    return l32[i * g_lblstride];
}

// ---------------- K0: zero scratch -----------------------------------------
__global__ void k_zero() {
    int t = blockIdx.x * blockDim.x + threadIdx.x;
    if (t < NROWS) g_denom[t] = 0.0f;
    if (t < 2 * DDIM) ((float*)g_M)[t] = 0.0f;
    if (t < 2) { g_cnt[t] = 0; g_acc[t] = 0.0f; }
}

// ---------------- K1: L2-normalize rows, write transposed ------------------
// one warp per row: lane l holds cols 4l..4l+3
__global__ void k_normalize(const float* __restrict__ emb) {
    int warp = (blockIdx.x * blockDim.x + threadIdx.x) >> 5;
    int lane = threadIdx.x & 31;
    if (warp >= NROWS) return;
    float4 v = ((const float4*)(emb + (size_t)warp * DDIM))[lane];
    float ss = v.x * v.x + v.y * v.y + v.z * v.z + v.w * v.w;
    #pragma unroll
    for (int o = 16; o; o >>= 1) ss += __shfl_xor_sync(0xffffffffu, ss, o);
    float r = rsqrtf(ss);
    int d = lane * 4;
    g_eT[(d + 0) * NROWS + warp] = v.x * r;
    g_eT[(d + 1) * NROWS + warp] = v.y * r;
    g_eT[(d + 2) * NROWS + warp] = v.z * r;
    g_eT[(d + 3) * NROWS + warp] = v.w * r;
}

// ---------------- K2: per-class sums M[c][d] -------------------------------
// one block per d; contention-free (no global atomics)
__global__ void k_classsum(const int* __restrict__ l32) {
    int d = blockIdx.x;
    int t = threadIdx.x;
    float a0 = 0.0f, a1 = 0.0f;
    for (int i = t; i < NROWS; i += 256) {
        float v = g_eT[d * NROWS + i];
        if (get_label(l32, i) == 0) a0 += v; else a1 += v;
    }
    __shared__ float s0[256], s1[256];
    s0[t] = a0; s1[t] = a1;
    __syncthreads();
    for (int st = 128; st; st >>= 1) {
        if (t < st) { s0[t] += s0[t + st]; s1[t] += s1[t + st]; }
        __syncthreads();
    }
    if (t == 0) { g_M[0][d] = s0[0]; g_M[1][d] = s1[0]; }
}

// ---------------- K2b: class counts ----------------------------------------
__global__ void k_count(const int* __restrict__ l32) {
    int t = threadIdx.x;
    int c0 = 0;
    for (int i = t; i < NROWS; i += 256) c0 += (get_label(l32, i) == 0);
    __shared__ int sc[256];
    sc[t] = c0;
    __syncthreads();
    for (int st = 128; st; st >>= 1) {
        if (t < st) sc[t] += sc[t + st];
        __syncthreads();
    }
    if (t == 0) { g_cnt[0] = sc[0]; g_cnt[1] = NROWS - sc[0]; }
}

// ---------------- K3: denom = rowsum of exp(e e^T), symmetric tiles --------
// 64x64 tile, 256 threads, 4x4 micro-tile. Both operands in [k][i] smem
// layout (stride 68 floats) -> conflict-free LDS.128 in the k-loop.
// Upper-triangle tiles only; off-diagonal tiles scatter row AND col sums.
__global__ void k_sim() {
    int bi = blockIdx.x;        // i-tile
    int bj = blockIdx.y;        // j-tile
    if (bi > bj) return;        // symmetry: only upper triangle

    extern __shared__ float smem[];
    float* As   = smem;                     // [128][68]
    float* Bs   = smem + DDIM * SMSTR;      // [128][68]
    float* cbuf = Bs   + DDIM * SMSTR;      // [64] column partial sums

    int i0 = bi * BT, j0 = bj * BT;
    int tid = threadIdx.x;

    // cooperative tile load: eT rows are contiguous in i -> coalesced LDG.128
    #pragma unroll
    for (int r = 0; r < 8; r++) {
        int flat = r * 256 + tid;           // 0..2047
        int k = flat >> 4;                  // 0..127
        int s = flat & 15;                  // float4 slot 0..15
        float4 va = *(const float4*)&g_eT[k * NROWS + i0 + s * 4];
        *(float4*)&As[k * SMSTR + s * 4] = va;
        float4 vb = *(const float4*)&g_eT[k * NROWS + j0 + s * 4];
        *(float4*)&Bs[k * SMSTR + s * 4] = vb;
    }
    if (tid < BT) cbuf[tid] = 0.0f;
    __syncthreads();

    int tx = tid & 15;          // j micro position
    int ty = tid >> 4;          // i micro position

    float acc[4][4] = {};
    #pragma unroll 8
    for (int k = 0; k < DDIM; k++) {
        float4 a = *(const float4*)&As[k * SMSTR + ty * 4];
        float4 b = *(const float4*)&Bs[k * SMSTR + tx * 4];
        acc[0][0] += a.x * b.x; acc[0][1] += a.x * b.y; acc[0][2] += a.x * b.z; acc[0][3] += a.x * b.w;
        acc[1][0] += a.y * b.x; acc[1][1] += a.y * b.y; acc[1][2] += a.y * b.z; acc[1][3] += a.y * b.w;
        acc[2][0] += a.z * b.x; acc[2][1] += a.z * b.y; acc[2][2] += a.z * b.z; acc[2][3] += a.z * b.w;
        acc[3][0] += a.w * b.x; acc[3][1] += a.w * b.y; acc[3][2] += a.w * b.z; acc[3][3] += a.w * b.w;
    }

    // exp + exclude diagonal exactly
    float rsum[4] = {0.f, 0.f, 0.f, 0.f};
    float csum[4] = {0.f, 0.f, 0.f, 0.f};
    #pragma unroll
    for (int m = 0; m < 4; m++) {
        int ig = i0 + ty * 4 + m;
        #pragma unroll
        for (int n = 0; n < 4; n++) {
            int jg = j0 + tx * 4 + n;
            float ex = (ig == jg) ? 0.0f : __expf(acc[m][n]);
            rsum[m] += ex;
            csum[n] += ex;
        }
    }

    // row sums: xor-shuffle over tx (16-lane groups; ty bits untouched)
    #pragma unroll
    for (int o = 8; o; o >>= 1) {
        #pragma unroll
        for (int m = 0; m < 4; m++)
            rsum[m] += __shfl_xor_sync(0xffffffffu, rsum[m], o);
    }
    if (tx == 0) {
        #pragma unroll
        for (int m = 0; m < 4; m++)
            atomicAdd(&g_denom[i0 + ty * 4 + m], rsum[m]);
    }

    // column sums (mirror contribution) — only for off-diagonal tiles
    if (bi != bj) {
        #pragma unroll
        for (int n = 0; n < 4; n++)
            atomicAdd(&cbuf[tx * 4 + n], csum[n]);
        __syncthreads();
        if (tid < BT) atomicAdd(&g_denom[j0 + tid], cbuf[tid]);
    }
}

// ---------------- K4: per-row loss + per-class block-reduced accumulate ----
__global__ void k_loss(const int* __restrict__ l32) {
    int i = blockIdx.x * 256 + threadIdx.x;
    int t = threadIdx.x;
    int c = (get_label(l32, i) == 0) ? 0 : 1;
    const float* Mc = g_M[c];
    float pos = 0.0f;
    #pragma unroll 16
    for (int d = 0; d < DDIM; d++)
        pos += g_eT[d * NROWS + i] * Mc[d];   // coalesced over i, Mc broadcast
    pos -= 1.0f;                              // remove the j==i term (|e_i|^2 = 1)
    float cntm1 = (float)(g_cnt[c] - 1);
    float li = -(pos - cntm1 * logf(g_denom[i]));

    __shared__ float sh0[256], sh1[256];
    sh0[t] = (c == 0) ? li : 0.0f;
    sh1[t] = (c == 0) ? 0.0f : li;
    __syncthreads();
    for (int st = 128; st; st >>= 1) {
        if (t < st) { sh0[t] += sh0[t + st]; sh1[t] += sh1[t + st]; }
        __syncthreads();
    }
    if (t == 0) {
        atomicAdd(&g_acc[0], sh0[0]);
        atomicAdd(&g_acc[1], sh1[0]);
    }
}

// ---------------- K5: final combine ----------------------------------------
__global__ void k_final(float* out) {
    out[0] = g_acc[0] / (float)g_cnt[0] + g_acc[1];
}

// ---------------- launch ----------------------------------------------------
extern "C" void kernel_launch(void* const* d_in, const int* in_sizes, int n_in,
                              void* d_out, int out_size) {
    const float* emb = (const float*)d_in[0];
    const int*   l32 = (const int*)d_in[1];   // int32 OR int64 viewed as int32
    float*       out = (float*)d_out;

    const int smem_bytes = (2 * DDIM * SMSTR + BT) * (int)sizeof(float); // 69,888 B
    cudaFuncSetAttribute(k_sim, cudaFuncAttributeMaxDynamicSharedMemorySize, smem_bytes);

    // label dtype detection (reads only the guaranteed-present 8192 int32 words)
    k_detect_pre<<<1, 1>>>();
    k_detect<<<NROWS / 2 / 256, 256>>>(l32);
    k_detect_post<<<1, 1>>>();

    k_zero<<<32, 256>>>();
    k_normalize<<<(NROWS * 32) / 256, 256>>>(emb);
    k_classsum<<<DDIM, 256>>>(l32);
    k_count<<<1, 256>>>(l32);

    dim3 grid(NROWS / BT, NROWS / BT);     // 128 x 128, lower triangle early-exits
    k_sim<<<grid, 256, smem_bytes>>>();

    k_loss<<<NROWS / 256, 256>>>(l32);
    k_final<<<1, 1>>>(out);
}

// round 4
// speedup vs baseline: 1.9409x; 1.9409x over previous
#include <cuda_runtime.h>
#include <cuda_bf16.h>
#include <math.h>
#include <cstdint>

// Problem constants (fixed by reference setup_inputs)
#define NROWS 8192
#define DDIM  128
#define TILE  128            // CTA output tile edge

// ---------------- scratch (no allocation allowed -> __device__ globals) ----
__device__ float         g_eT[DDIM * NROWS];  // normalized, TRANSPOSED [d][i] (4 MB)
__device__ __nv_bfloat16 g_ebf[NROWS * DDIM]; // normalized * sqrt(log2e), row-major [i][d]
__device__ float g_denom[NROWS];
__device__ float g_M[2][DDIM];
__device__ int   g_cnt[2];
__device__ float g_acc[2];
__device__ int   g_lblstride;
__device__ int   g_oddnz;

// ---------------- helpers ---------------------------------------------------
__device__ __forceinline__ uint32_t smem_u32(const void* p) {
    uint32_t a;
    asm("{ .reg .u64 t; cvta.to.shared.u64 t, %1; cvt.u32.u64 %0, t; }" : "=r"(a) : "l"(p));
    return a;
}
__device__ __forceinline__ float ex2f(float x) {
    float r;
    asm("ex2.approx.ftz.f32 %0, %1;" : "=f"(r) : "f"(x));
    return r;
}
__device__ __forceinline__ void ldsm_x4(uint32_t a, uint32_t& r0, uint32_t& r1,
                                        uint32_t& r2, uint32_t& r3) {
    asm volatile("ldmatrix.sync.aligned.m8n8.x4.shared.b16 {%0,%1,%2,%3}, [%4];"
                 : "=r"(r0), "=r"(r1), "=r"(r2), "=r"(r3) : "r"(a));
}
__device__ __forceinline__ void ldsm_x2t(uint32_t a, uint32_t& r0, uint32_t& r1) {
    asm volatile("ldmatrix.sync.aligned.m8n8.x2.trans.shared.b16 {%0,%1}, [%2];"
                 : "=r"(r0), "=r"(r1) : "r"(a));
}
__device__ __forceinline__ void mma16816(float* c, uint32_t a0, uint32_t a1,
                                         uint32_t a2, uint32_t a3,
                                         uint32_t b0, uint32_t b1) {
    asm volatile(
        "mma.sync.aligned.m16n8k16.row.col.f32.bf16.bf16.f32 "
        "{%0,%1,%2,%3}, {%4,%5,%6,%7}, {%8,%9}, {%0,%1,%2,%3};"
        : "+f"(c[0]), "+f"(c[1]), "+f"(c[2]), "+f"(c[3])
        : "r"(a0), "r"(a1), "r"(a2), "r"(a3), "r"(b0), "r"(b1));
}

// ---------------- label dtype sniffing (int32 vs int64 low-word) -----------
__global__ void k_detect_pre() { g_oddnz = 0; }
__global__ void k_detect(const int* __restrict__ l32) {
    int t = blockIdx.x * blockDim.x + threadIdx.x;
    if (l32[2 * t + 1] != 0) atomicOr(&g_oddnz, 1);
}
__global__ void k_detect_post() { g_lblstride = g_oddnz ? 1 : 2; }
__device__ __forceinline__ int get_label(const int* l32, int i) { return l32[i * g_lblstride]; }

// ---------------- K0: zero scratch -----------------------------------------
__global__ void k_zero() {
    int t = blockIdx.x * blockDim.x + threadIdx.x;
    if (t < NROWS) g_denom[t] = 0.0f;
    if (t < 2 * DDIM) ((float*)g_M)[t] = 0.0f;
    if (t < 2) { g_cnt[t] = 0; g_acc[t] = 0.0f; }
}

// ---------------- K1: L2-normalize; write fp32-transposed + bf16-scaled ----
__global__ void k_normalize(const float* __restrict__ emb) {
    const float SQRT_LOG2E = 1.2011224087864498f;  // sqrt(1/ln 2)
    int warp = (blockIdx.x * blockDim.x + threadIdx.x) >> 5;
    int lane = threadIdx.x & 31;
    if (warp >= NROWS) return;
    float4 v = ((const float4*)(emb + (size_t)warp * DDIM))[lane];
    float ss = v.x * v.x + v.y * v.y + v.z * v.z + v.w * v.w;
    #pragma unroll
    for (int o = 16; o; o >>= 1) ss += __shfl_xor_sync(0xffffffffu, ss, o);
    float r = rsqrtf(ss);
    int d = lane * 4;
    g_eT[(d + 0) * NROWS + warp] = v.x * r;
    g_eT[(d + 1) * NROWS + warp] = v.y * r;
    g_eT[(d + 2) * NROWS + warp] = v.z * r;
    g_eT[(d + 3) * NROWS + warp] = v.w * r;
    float s = r * SQRT_LOG2E;
    __nv_bfloat162 b01 = __floats2bfloat162_rn(v.x * s, v.y * s);
    __nv_bfloat162 b23 = __floats2bfloat162_rn(v.z * s, v.w * s);
    *(__nv_bfloat162*)&g_ebf[(size_t)warp * DDIM + d]     = b01;
    *(__nv_bfloat162*)&g_ebf[(size_t)warp * DDIM + d + 2] = b23;
}

// ---------------- K2: per-class sums M[c][d] -------------------------------
__global__ void k_classsum(const int* __restrict__ l32) {
    int d = blockIdx.x, t = threadIdx.x;
    float a0 = 0.0f, a1 = 0.0f;
    for (int i = t; i < NROWS; i += 256) {
        float v = g_eT[d * NROWS + i];
        if (get_label(l32, i) == 0) a0 += v; else a1 += v;
    }
    __shared__ float s0[256], s1[256];
    s0[t] = a0; s1[t] = a1;
    __syncthreads();
    for (int st = 128; st; st >>= 1) {
        if (t < st) { s0[t] += s0[t + st]; s1[t] += s1[t + st]; }
        __syncthreads();
    }
    if (t == 0) { g_M[0][d] = s0[0]; g_M[1][d] = s1[0]; }
}

__global__ void k_count(const int* __restrict__ l32) {
    int t = threadIdx.x, c0 = 0;
    for (int i = t; i < NROWS; i += 256) c0 += (get_label(l32, i) == 0);
    __shared__ int sc[256];
    sc[t] = c0;
    __syncthreads();
    for (int st = 128; st; st >>= 1) {
        if (t < st) sc[t] += sc[t + st];
        __syncthreads();
    }
    if (t == 0) { g_cnt[0] = sc[0]; g_cnt[1] = NROWS - sc[0]; }
}

// ---------------- K3: HMMA sim tile + ex2 rowsum epilogue ------------------
// One CTA = one 128x128 tile of sim*log2e (full matrix: rowsums thread-local).
// 8 warps as 2(m) x 4(n); warp tile 64x32; mma.m16n8k16 bf16 -> f32.
// SMEM tile layout: row-major 256B rows; 16B chunk c of row r stored at
// chunk (c ^ (r&7)) -> conflict-free ldmatrix and stores.
#define SM_A   0
#define SM_B   32768
#define SM_RED 65536
#define SM_TOT 66048

__global__ void __launch_bounds__(256, 2) k_sim() {
    extern __shared__ char smem[];
    uint32_t sb = smem_u32(smem);
    int tid = threadIdx.x;
    int wid = tid >> 5, lane = tid & 31;
    int i0 = blockIdx.x * TILE, j0 = blockIdx.y * TILE;
    bool diag_tile = (blockIdx.x == blockIdx.y);

    float* red = (float*)(smem + SM_RED);
    if (tid < TILE) red[tid] = 0.0f;

    // ---- load A (rows i0..) and B (rows j0..) tiles, swizzled ----
    {
        int row = tid >> 1;             // 0..127
        int half = tid & 1;             // which 8 chunks
        const uint4* arow = (const uint4*)&g_ebf[(size_t)(i0 + row) * DDIM];
        const uint4* brow = (const uint4*)&g_ebf[(size_t)(j0 + row) * DDIM];
        #pragma unroll
        for (int c = 0; c < 8; c++) {
            int chunk = half * 8 + c;
            uint32_t off = row * 256 + ((chunk ^ (row & 7)) << 4);
            *(uint4*)(smem + SM_A + off) = arow[chunk];
            *(uint4*)(smem + SM_B + off) = brow[chunk];
        }
    }
    __syncthreads();

    int m_off = (wid >> 2) * 64;        // 0 or 64
    int n_off = (wid & 3) * 32;         // 0,32,64,96

    float acc[4][4][4];                  // [mt][nt][frag]
    #pragma unroll
    for (int mt = 0; mt < 4; mt++)
        #pragma unroll
        for (int nt = 0; nt < 4; nt++)
            #pragma unroll
            for (int e = 0; e < 4; e++) acc[mt][nt][e] = 0.0f;

    // per-lane base addresses
    uint32_t rowA = (uint32_t)(m_off + (lane & 15));
    uint32_t rowB = (uint32_t)(n_off + (lane & 7));
    uint32_t swzA = (uint32_t)(lane & 7);   // rowA & 7 == lane & 7
    uint32_t swzB = (uint32_t)(lane & 7);

    #pragma unroll
    for (int kk = 0; kk < 8; kk++) {
        uint32_t a0[4], a1[4], a2[4], a3[4];
        #pragma unroll
        for (int mt = 0; mt < 4; mt++) {
            uint32_t chunk = (uint32_t)(kk * 2 + (lane >> 4));
            uint32_t addr = sb + SM_A + (rowA + mt * 16) * 256 + ((chunk ^ swzA) << 4);
            ldsm_x4(addr, a0[mt], a1[mt], a2[mt], a3[mt]);
        }
        uint32_t b0[4], b1[4];
        #pragma unroll
        for (int nt = 0; nt < 4; nt++) {
            uint32_t chunk = (uint32_t)(kk * 2 + ((lane >> 3) & 1));
            uint32_t addr = sb + SM_B + (rowB + nt * 8) * 256 + ((chunk ^ swzB) << 4);
            ldsm_x2t(addr, b0[nt], b1[nt]);
        }
        #pragma unroll
        for (int mt = 0; mt < 4; mt++)
            #pragma unroll
            for (int nt = 0; nt < 4; nt++)
                mma16816(acc[mt][nt], a0[mt], a1[mt], a2[mt], a3[mt], b0[nt], b1[nt]);
    }

    // ---- epilogue: exp2 + thread-local row sums ----
    // frag e: row = lane>>2 (+8 for e>=2), col = (lane&3)*2 + (e&1)
    int lrow = lane >> 2;
    int lcol = (lane & 3) * 2;
    #pragma unroll
    for (int mt = 0; mt < 4; mt++) {
        float s0 = 0.0f, s1 = 0.0f;
        int grow0 = i0 + m_off + mt * 16 + lrow;
        #pragma unroll
        for (int nt = 0; nt < 4; nt++) {
            int gcol = j0 + n_off + nt * 8 + lcol;
            float e0 = ex2f(acc[mt][nt][0]);
            float e1 = ex2f(acc[mt][nt][1]);
            float e2 = ex2f(acc[mt][nt][2]);
            float e3 = ex2f(acc[mt][nt][3]);
            if (diag_tile) {
                if (gcol     == grow0)     e0 = 0.0f;
                if (gcol + 1 == grow0)     e1 = 0.0f;
                if (gcol     == grow0 + 8) e2 = 0.0f;
                if (gcol + 1 == grow0 + 8) e3 = 0.0f;
            }
            s0 += e0 + e1;
            s1 += e2 + e3;
        }
        // reduce across the 4 lanes sharing a row (xor bits 0,1)
        s0 += __shfl_xor_sync(0xffffffffu, s0, 1);
        s0 += __shfl_xor_sync(0xffffffffu, s0, 2);
        s1 += __shfl_xor_sync(0xffffffffu, s1, 1);
        s1 += __shfl_xor_sync(0xffffffffu, s1, 2);
        if ((lane & 3) == 0) {
            atomicAdd(&red[m_off + mt * 16 + lrow], s0);
            atomicAdd(&red[m_off + mt * 16 + lrow + 8], s1);
        }
    }
    __syncthreads();
    if (tid < TILE) atomicAdd(&g_denom[i0 + tid], red[tid]);
}

// ---------------- K4: per-row loss + per-class reduce ----------------------
__global__ void k_loss(const int* __restrict__ l32) {
    int i = blockIdx.x * 256 + threadIdx.x;
    int t = threadIdx.x;
    int c = (get_label(l32, i) == 0) ? 0 : 1;
    const float* Mc = g_M[c];
    float pos = 0.0f;
    #pragma unroll 16
    for (int d = 0; d < DDIM; d++)
        pos += g_eT[d * NROWS + i] * Mc[d];
    pos -= 1.0f;
    float cntm1 = (float)(g_cnt[c] - 1);
    float li = -(pos - cntm1 * logf(g_denom[i]));

    __shared__ float sh0[256], sh1[256];
    sh0[t] = (c == 0) ? li : 0.0f;
    sh1[t] = (c == 0) ? 0.0f : li;
    __syncthreads();
    for (int st = 128; st; st >>= 1) {
        if (t < st) { sh0[t] += sh0[t + st]; sh1[t] += sh1[t + st]; }
        __syncthreads();
    }
    if (t == 0) { atomicAdd(&g_acc[0], sh0[0]); atomicAdd(&g_acc[1], sh1[0]); }
}

__global__ void k_final(float* out) {
    out[0] = g_acc[0] / (float)g_cnt[0] + g_acc[1];
}

// ---------------- launch ----------------------------------------------------
extern "C" void kernel_launch(void* const* d_in, const int* in_sizes, int n_in,
                              void* d_out, int out_size) {
    const float* emb = (const float*)d_in[0];
    const int*   l32 = (const int*)d_in[1];
    float*       out = (float*)d_out;

    cudaFuncSetAttribute(k_sim, cudaFuncAttributeMaxDynamicSharedMemorySize, SM_TOT);

    k_detect_pre<<<1, 1>>>();
    k_detect<<<NROWS / 2 / 256, 256>>>(l32);
    k_detect_post<<<1, 1>>>();

    k_zero<<<32, 256>>>();
    k_normalize<<<(NROWS * 32) / 256, 256>>>(emb);
    k_classsum<<<DDIM, 256>>>(l32);
    k_count<<<1, 256>>>(l32);

    dim3 grid(NROWS / TILE, NROWS / TILE);   // 64 x 64 tiles
    k_sim<<<grid, 256, SM_TOT>>>();

    k_loss<<<NROWS / 256, 256>>>(l32);
    k_final<<<1, 1>>>(out);
}

// round 5
// speedup vs baseline: 2.9172x; 1.5031x over previous
#include <cuda_runtime.h>
#include <cuda_bf16.h>
#include <math.h>
#include <cstdint>

#define NROWS 8192
#define DDIM  128
#define TILE  128
#define NTILE (NROWS / TILE)            // 64
#define NTRI  (NTILE * (NTILE + 1) / 2) // 2080 upper-triangle tiles

// ---------------- scratch ----------------------------------------------------
__device__ float         g_eT[DDIM * NROWS];
__device__ __nv_bfloat16 g_ebf[NROWS * DDIM];
__device__ float g_denom[NROWS];
__device__ float g_M[2][DDIM];
__device__ int   g_cnt[2];
__device__ float g_acc[2];
__device__ int   g_lblstride;
__device__ int   g_done;

// ---------------- helpers ----------------------------------------------------
__device__ __forceinline__ uint32_t smem_u32(const void* p) {
    uint32_t a;
    asm("{ .reg .u64 t; cvta.to.shared.u64 t, %1; cvt.u32.u64 %0, t; }" : "=r"(a) : "l"(p));
    return a;
}
__device__ __forceinline__ float ex2f(float x) {
    float r;
    asm("ex2.approx.ftz.f32 %0, %1;" : "=f"(r) : "f"(x));
    return r;
}
__device__ __forceinline__ void ldsm_x4(uint32_t a, uint32_t& r0, uint32_t& r1,
                                        uint32_t& r2, uint32_t& r3) {
    asm volatile("ldmatrix.sync.aligned.m8n8.x4.shared.b16 {%0,%1,%2,%3}, [%4];"
                 : "=r"(r0), "=r"(r1), "=r"(r2), "=r"(r3) : "r"(a));
}
__device__ __forceinline__ void ldsm_x2t(uint32_t a, uint32_t& r0, uint32_t& r1) {
    asm volatile("ldmatrix.sync.aligned.m8n8.x2.trans.shared.b16 {%0,%1}, [%2];"
                 : "=r"(r0), "=r"(r1) : "r"(a));
}
__device__ __forceinline__ void mma16816(float* c, uint32_t a0, uint32_t a1,
                                         uint32_t a2, uint32_t a3,
                                         uint32_t b0, uint32_t b1) {
    asm volatile(
        "mma.sync.aligned.m16n8k16.row.col.f32.bf16.bf16.f32 "
        "{%0,%1,%2,%3}, {%4,%5,%6,%7}, {%8,%9}, {%0,%1,%2,%3};"
        : "+f"(c[0]), "+f"(c[1]), "+f"(c[2]), "+f"(c[3])
        : "r"(a0), "r"(a1), "r"(a2), "r"(a3), "r"(b0), "r"(b1));
}
__device__ __forceinline__ int get_label(const int* l32, int i) { return l32[i * g_lblstride]; }

// ---------------- K_init: zero scratch + label-dtype detection (fused) -----
// blocks 0..31: zero g_denom etc.; block 32: sniff int64-vs-int32 labels.
__global__ void k_init(const int* __restrict__ l32) {
    if (blockIdx.x < 32) {
        int t = blockIdx.x * 256 + threadIdx.x;
        if (t < NROWS) g_denom[t] = 0.0f;
        if (t < 2 * DDIM) ((float*)g_M)[t] = 0.0f;
        if (t < 2) { g_cnt[t] = 0; g_acc[t] = 0.0f; }
        if (t == 0) g_done = 0;
    } else {
        // labels are 0/1; int64 LE => every odd int32 word is zero
        int t = threadIdx.x, nz = 0;
        for (int i = t; i < NROWS / 2; i += 256) nz |= l32[2 * i + 1];
        __shared__ int s;
        if (t == 0) s = 0;
        __syncthreads();
        if (nz) atomicOr(&s, 1);
        __syncthreads();
        if (t == 0) g_lblstride = s ? 1 : 2;
    }
}

// ---------------- K1: L2-normalize; fp32-transposed + bf16*sqrt(log2e) -----
__global__ void k_normalize(const float* __restrict__ emb) {
    const float SQRT_LOG2E = 1.2011224087864498f;
    int warp = (blockIdx.x * blockDim.x + threadIdx.x) >> 5;
    int lane = threadIdx.x & 31;
    if (warp >= NROWS) return;
    float4 v = ((const float4*)(emb + (size_t)warp * DDIM))[lane];
    float ss = v.x * v.x + v.y * v.y + v.z * v.z + v.w * v.w;
    #pragma unroll
    for (int o = 16; o; o >>= 1) ss += __shfl_xor_sync(0xffffffffu, ss, o);
    float r = rsqrtf(ss);
    int d = lane * 4;
    g_eT[(d + 0) * NROWS + warp] = v.x * r;
    g_eT[(d + 1) * NROWS + warp] = v.y * r;
    g_eT[(d + 2) * NROWS + warp] = v.z * r;
    g_eT[(d + 3) * NROWS + warp] = v.w * r;
    float s = r * SQRT_LOG2E;
    __nv_bfloat162 b01 = __floats2bfloat162_rn(v.x * s, v.y * s);
    __nv_bfloat162 b23 = __floats2bfloat162_rn(v.z * s, v.w * s);
    *(__nv_bfloat162*)&g_ebf[(size_t)warp * DDIM + d]     = b01;
    *(__nv_bfloat162*)&g_ebf[(size_t)warp * DDIM + d + 2] = b23;
}

// ---------------- K2: per-class sums (block per d) + counts (block 0) ------
__global__ void k_classsum(const int* __restrict__ l32) {
    int d = blockIdx.x, t = threadIdx.x;
    float a0 = 0.0f, a1 = 0.0f;
    int c0 = 0;
    for (int i = t; i < NROWS; i += 256) {
        float v = g_eT[d * NROWS + i];
        int lab = get_label(l32, i);
        if (lab == 0) { a0 += v; c0++; } else a1 += v;
    }
    __shared__ float s0[256], s1[256];
    __shared__ int   sc[256];
    s0[t] = a0; s1[t] = a1; sc[t] = c0;
    __syncthreads();
    for (int st = 128; st; st >>= 1) {
        if (t < st) { s0[t] += s0[t + st]; s1[t] += s1[t + st]; sc[t] += sc[t + st]; }
        __syncthreads();
    }
    if (t == 0) {
        g_M[0][d] = s0[0]; g_M[1][d] = s1[0];
        if (d == 0) { g_cnt[0] = sc[0]; g_cnt[1] = NROWS - sc[0]; }
    }
}

// ---------------- K3: HMMA sim tiles, UPPER TRIANGLE ONLY -------------------
// off-diagonal tiles scatter row sums (i-rows) AND column sums (j-rows).
#define SM_A   0
#define SM_B   32768
#define SM_RED 65536           // 128 row sums
#define SM_REDC 66048          // 128 col sums
#define SM_TOT 66560

__global__ void __launch_bounds__(256, 2) k_sim() {
    // triangular decode: idx -> (bi, bj), bi <= bj
    int idx = blockIdx.x;
    int bj = (int)((sqrtf(8.0f * (float)idx + 1.0f) - 1.0f) * 0.5f);
    while ((bj + 1) * (bj + 2) / 2 <= idx) bj++;
    while (bj * (bj + 1) / 2 > idx) bj--;
    int bi = idx - bj * (bj + 1) / 2;

    extern __shared__ char smem[];
    uint32_t sb = smem_u32(smem);
    int tid = threadIdx.x;
    int wid = tid >> 5, lane = tid & 31;
    int i0 = bi * TILE, j0 = bj * TILE;
    bool diag_tile = (bi == bj);

    float* red  = (float*)(smem + SM_RED);
    float* redc = (float*)(smem + SM_REDC);
    if (tid < TILE) { red[tid] = 0.0f; redc[tid] = 0.0f; }

    // tile loads (swizzled: 16B chunk c of row r at chunk c^(r&7))
    {
        int row = tid >> 1;
        int half = tid & 1;
        const uint4* arow = (const uint4*)&g_ebf[(size_t)(i0 + row) * DDIM];
        const uint4* brow = (const uint4*)&g_ebf[(size_t)(j0 + row) * DDIM];
        #pragma unroll
        for (int c = 0; c < 8; c++) {
            int chunk = half * 8 + c;
            uint32_t off = row * 256 + ((chunk ^ (row & 7)) << 4);
            *(uint4*)(smem + SM_A + off) = arow[chunk];
            *(uint4*)(smem + SM_B + off) = brow[chunk];
        }
    }
    __syncthreads();

    int m_off = (wid >> 2) * 64;
    int n_off = (wid & 3) * 32;

    float acc[4][4][4];
    #pragma unroll
    for (int mt = 0; mt < 4; mt++)
        #pragma unroll
        for (int nt = 0; nt < 4; nt++)
            #pragma unroll
            for (int e = 0; e < 4; e++) acc[mt][nt][e] = 0.0f;

    uint32_t rowA = (uint32_t)(m_off + (lane & 15));
    uint32_t rowB = (uint32_t)(n_off + (lane & 7));
    uint32_t swz  = (uint32_t)(lane & 7);

    #pragma unroll
    for (int kk = 0; kk < 8; kk++) {
        uint32_t a0[4], a1[4], a2[4], a3[4];
        #pragma unroll
        for (int mt = 0; mt < 4; mt++) {
            uint32_t chunk = (uint32_t)(kk * 2 + (lane >> 4));
            uint32_t addr = sb + SM_A + (rowA + mt * 16) * 256 + ((chunk ^ swz) << 4);
            ldsm_x4(addr, a0[mt], a1[mt], a2[mt], a3[mt]);
        }
        uint32_t b0[4], b1[4];
        #pragma unroll
        for (int nt = 0; nt < 4; nt++) {
            uint32_t chunk = (uint32_t)(kk * 2 + ((lane >> 3) & 1));
            uint32_t addr = sb + SM_B + (rowB + nt * 8) * 256 + ((chunk ^ swz) << 4);
            ldsm_x2t(addr, b0[nt], b1[nt]);
        }
        #pragma unroll
        for (int mt = 0; mt < 4; mt++)
            #pragma unroll
            for (int nt = 0; nt < 4; nt++)
                mma16816(acc[mt][nt], a0[mt], a1[mt], a2[mt], a3[mt], b0[nt], b1[nt]);
    }

    // ---- epilogue: ex2, row sums, and (off-diag) column sums ----
    int lrow = lane >> 2;
    int lcol = (lane & 3) * 2;
    float colacc[4][2];
    #pragma unroll
    for (int nt = 0; nt < 4; nt++) { colacc[nt][0] = 0.0f; colacc[nt][1] = 0.0f; }

    #pragma unroll
    for (int mt = 0; mt < 4; mt++) {
        float s0 = 0.0f, s1 = 0.0f;
        int grow0 = i0 + m_off + mt * 16 + lrow;
        #pragma unroll
        for (int nt = 0; nt < 4; nt++) {
            int gcol = j0 + n_off + nt * 8 + lcol;
            float e0 = ex2f(acc[mt][nt][0]);
            float e1 = ex2f(acc[mt][nt][1]);
            float e2 = ex2f(acc[mt][nt][2]);
            float e3 = ex2f(acc[mt][nt][3]);
            if (diag_tile) {
                if (gcol     == grow0)     e0 = 0.0f;
                if (gcol + 1 == grow0)     e1 = 0.0f;
                if (gcol     == grow0 + 8) e2 = 0.0f;
                if (gcol + 1 == grow0 + 8) e3 = 0.0f;
            }
            s0 += e0 + e1;
            s1 += e2 + e3;
            colacc[nt][0] += e0 + e2;
            colacc[nt][1] += e1 + e3;
        }
        s0 += __shfl_xor_sync(0xffffffffu, s0, 1);
        s0 += __shfl_xor_sync(0xffffffffu, s0, 2);
        s1 += __shfl_xor_sync(0xffffffffu, s1, 1);
        s1 += __shfl_xor_sync(0xffffffffu, s1, 2);
        if ((lane & 3) == 0) {
            atomicAdd(&red[m_off + mt * 16 + lrow], s0);
            atomicAdd(&red[m_off + mt * 16 + lrow + 8], s1);
        }
    }

    if (!diag_tile) {
        // reduce columns over the 8 lanes sharing (lane&3)
        #pragma unroll
        for (int nt = 0; nt < 4; nt++) {
            #pragma unroll
            for (int h = 0; h < 2; h++) {
                float c = colacc[nt][h];
                c += __shfl_xor_sync(0xffffffffu, c, 4);
                c += __shfl_xor_sync(0xffffffffu, c, 8);
                c += __shfl_xor_sync(0xffffffffu, c, 16);
                if (lane < 4)   // lane>>2 == 0 holds the total for col (lane&3)*2+h
                    atomicAdd(&redc[n_off + nt * 8 + (lane & 3) * 2 + h], c);
            }
        }
    }

    __syncthreads();
    if (tid < TILE) {
        atomicAdd(&g_denom[i0 + tid], red[tid]);
        if (!diag_tile) atomicAdd(&g_denom[j0 + tid], redc[tid]);
    }
}

// ---------------- K4: per-row loss + per-class reduce + fused final --------
__global__ void k_loss(const int* __restrict__ l32, float* __restrict__ out) {
    int i = blockIdx.x * 256 + threadIdx.x;
    int t = threadIdx.x;
    int c = (get_label(l32, i) == 0) ? 0 : 1;
    const float* Mc = g_M[c];
    float pos = 0.0f;
    #pragma unroll 16
    for (int d = 0; d < DDIM; d++)
        pos += g_eT[d * NROWS + i] * Mc[d];
    pos -= 1.0f;
    float cntm1 = (float)(g_cnt[c] - 1);
    float li = -(pos - cntm1 * logf(g_denom[i]));

    __shared__ float sh0[256], sh1[256];
    sh0[t] = (c == 0) ? li : 0.0f;
    sh1[t] = (c == 0) ? 0.0f : li;
    __syncthreads();
    for (int st = 128; st; st >>= 1) {
        if (t < st) { sh0[t] += sh0[t + st]; sh1[t] += sh1[t + st]; }
        __syncthreads();
    }
    __shared__ int ticket;
    if (t == 0) {
        atomicAdd(&g_acc[0], sh0[0]);
        atomicAdd(&g_acc[1], sh1[0]);
        __threadfence();
        ticket = atomicAdd(&g_done, 1);
    }
    __syncthreads();
    if (t == 0 && ticket == gridDim.x - 1) {
        out[0] = g_acc[0] / (float)g_cnt[0] + g_acc[1];
    }
}

// ---------------- launch -----------------------------------------------------
extern "C" void kernel_launch(void* const* d_in, const int* in_sizes, int n_in,
                              void* d_out, int out_size) {
    const float* emb = (const float*)d_in[0];
    const int*   l32 = (const int*)d_in[1];
    float*       out = (float*)d_out;

    cudaFuncSetAttribute(k_sim, cudaFuncAttributeMaxDynamicSharedMemorySize, SM_TOT);

    k_init<<<33, 256>>>(l32);
    k_normalize<<<(NROWS * 32) / 256, 256>>>(emb);
    k_classsum<<<DDIM, 256>>>(l32);
    k_sim<<<NTRI, 256, SM_TOT>>>();
    k_loss<<<NROWS / 256, 256>>>(l32, out);
}

// round 6
// speedup vs baseline: 2.9625x; 1.0155x over previous
#include <cuda_runtime.h>
#include <cuda_fp16.h>
#include <math.h>
#include <cstdint>

#define NROWS 8192
#define DDIM  128

// ---------------- scratch ----------------------------------------------------
__device__ float  g_eT[DDIM * NROWS];   // normalized fp32, transposed [d][i]
__device__ __half g_eh[NROWS * DDIM];   // normalized * sqrt(log2e), fp16 [i][d]
__device__ float g_denom[NROWS];
__device__ float g_M[2][DDIM];
__device__ int   g_cnt[2];
__device__ float g_acc[2];
__device__ int   g_lblstride;
__device__ int   g_done;

// ---------------- helpers ----------------------------------------------------
__device__ __forceinline__ uint32_t smem_u32(const void* p) {
    uint32_t a;
    asm("{ .reg .u64 t; cvta.to.shared.u64 t, %1; cvt.u32.u64 %0, t; }" : "=r"(a) : "l"(p));
    return a;
}
__device__ __forceinline__ float ex2f(float x) {
    float r;
    asm("ex2.approx.ftz.f32 %0, %1;" : "=f"(r) : "f"(x));
    return r;
}
__device__ __forceinline__ void ldsm_x4(uint32_t a, uint32_t& r0, uint32_t& r1,
                                        uint32_t& r2, uint32_t& r3) {
    asm volatile("ldmatrix.sync.aligned.m8n8.x4.shared.b16 {%0,%1,%2,%3}, [%4];"
                 : "=r"(r0), "=r"(r1), "=r"(r2), "=r"(r3) : "r"(a));
}
__device__ __forceinline__ void ldsm_x4t(uint32_t a, uint32_t& r0, uint32_t& r1,
                                         uint32_t& r2, uint32_t& r3) {
    asm volatile("ldmatrix.sync.aligned.m8n8.x4.trans.shared.b16 {%0,%1,%2,%3}, [%4];"
                 : "=r"(r0), "=r"(r1), "=r"(r2), "=r"(r3) : "r"(a));
}
__device__ __forceinline__ void mma16816h(uint32_t* c, uint32_t a0, uint32_t a1,
                                          uint32_t a2, uint32_t a3,
                                          uint32_t b0, uint32_t b1) {
    asm volatile(
        "mma.sync.aligned.m16n8k16.row.col.f16.f16.f16.f16 "
        "{%0,%1}, {%2,%3,%4,%5}, {%6,%7}, {%0,%1};"
        : "+r"(c[0]), "+r"(c[1])
        : "r"(a0), "r"(a1), "r"(a2), "r"(a3), "r"(b0), "r"(b1));
}
__device__ __forceinline__ int get_label(const int* l32, int i) { return l32[i * g_lblstride]; }

// ---------------- K_init: zero + label-dtype sniff --------------------------
__global__ void k_init(const int* __restrict__ l32) {
    if (blockIdx.x < 32) {
        int t = blockIdx.x * 256 + threadIdx.x;
        if (t < NROWS) g_denom[t] = 0.0f;
        if (t < 2 * DDIM) ((float*)g_M)[t] = 0.0f;
        if (t < 2) { g_cnt[t] = 0; g_acc[t] = 0.0f; }
        if (t == 0) g_done = 0;
    } else {
        int t = threadIdx.x, nz = 0;
        for (int i = t; i < NROWS / 2; i += 256) nz |= l32[2 * i + 1];
        __shared__ int s;
        if (t == 0) s = 0;
        __syncthreads();
        if (nz) atomicOr(&s, 1);
        __syncthreads();
        if (t == 0) g_lblstride = s ? 1 : 2;
    }
}

// ---------------- K1: L2-normalize -> fp32 transposed + fp16*sqrt(log2e) ----
__global__ void k_normalize(const float* __restrict__ emb) {
    const float SQRT_LOG2E = 1.2011224087864498f;
    int warp = (blockIdx.x * blockDim.x + threadIdx.x) >> 5;
    int lane = threadIdx.x & 31;
    if (warp >= NROWS) return;
    float4 v = ((const float4*)(emb + (size_t)warp * DDIM))[lane];
    float ss = v.x * v.x + v.y * v.y + v.z * v.z + v.w * v.w;
    #pragma unroll
    for (int o = 16; o; o >>= 1) ss += __shfl_xor_sync(0xffffffffu, ss, o);
    float r = rsqrtf(ss);
    int d = lane * 4;
    g_eT[(d + 0) * NROWS + warp] = v.x * r;
    g_eT[(d + 1) * NROWS + warp] = v.y * r;
    g_eT[(d + 2) * NROWS + warp] = v.z * r;
    g_eT[(d + 3) * NROWS + warp] = v.w * r;
    float s = r * SQRT_LOG2E;
    __half2 h01 = __floats2half2_rn(v.x * s, v.y * s);
    __half2 h23 = __floats2half2_rn(v.z * s, v.w * s);
    *(__half2*)&g_eh[(size_t)warp * DDIM + d]     = h01;
    *(__half2*)&g_eh[(size_t)warp * DDIM + d + 2] = h23;
}

// ---------------- K2: per-class sums + counts --------------------------------
__global__ void k_classsum(const int* __restrict__ l32) {
    int d = blockIdx.x, t = threadIdx.x;
    float a0 = 0.0f, a1 = 0.0f;
    int c0 = 0;
    for (int i = t; i < NROWS; i += 256) {
        float v = g_eT[d * NROWS + i];
        if (get_label(l32, i) == 0) { a0 += v; c0++; } else a1 += v;
    }
    __shared__ float s0[256], s1[256];
    __shared__ int   sc[256];
    s0[t] = a0; s1[t] = a1; sc[t] = c0;
    __syncthreads();
    for (int st = 128; st; st >>= 1) {
        if (t < st) { s0[t] += s0[t + st]; s1[t] += s1[t + st]; sc[t] += sc[t + st]; }
        __syncthreads();
    }
    if (t == 0) {
        g_M[0][d] = s0[0]; g_M[1][d] = s1[0];
        if (d == 0) { g_cnt[0] = sc[0]; g_cnt[1] = NROWS - sc[0]; }
    }
}

// ---------------- K3: fp16 HMMA, CTA tile 256(m) x 128(n) -------------------
// 8 warps as 4(m) x 2(n), warp tile 64x64, f16 accumulators.
// grid (bj, bi2), valid when bj >= 2*bi2. CTA's two 128-row halves h=0,1 are
// i-tiles 2*bi2+h vs j-tile bj: diag when equal, skipped when below diagonal.
#define SM_A    0               // 256 rows x 256B = 65536
#define SM_B    65536           // 128 rows x 256B = 32768
#define SM_RED  98304           // 256 f32 row sums
#define SM_REDC 99328           // 128 f32 col sums
#define SM_TOT  99840

__global__ void __launch_bounds__(256, 2) k_sim() {
    int bj = blockIdx.x, bi2 = blockIdx.y;
    if (bj < 2 * bi2) return;

    extern __shared__ char smem[];
    uint32_t sb = smem_u32(smem);
    int tid = threadIdx.x;
    int wid = tid >> 5, lane = tid & 31;
    int i0 = bi2 * 256, j0 = bj * 128;

    float* red  = (float*)(smem + SM_RED);
    float* redc = (float*)(smem + SM_REDC);
    red[tid] = 0.0f;
    if (tid < 128) redc[tid] = 0.0f;

    // ---- tile loads (16B chunk c of row r stored at chunk c^(r&7)) ----
    {
        // A: 256 rows, one row per thread
        const uint4* arow = (const uint4*)&g_eh[(size_t)(i0 + tid) * DDIM];
        #pragma unroll
        for (int c = 0; c < 16; c++) {
            uint32_t off = tid * 256 + ((c ^ (tid & 7)) << 4);
            *(uint4*)(smem + SM_A + off) = arow[c];
        }
        // B: 128 rows, two threads per row
        int row = tid >> 1, half = tid & 1;
        const uint4* brow = (const uint4*)&g_eh[(size_t)(j0 + row) * DDIM];
        #pragma unroll
        for (int c = 0; c < 8; c++) {
            int chunk = half * 8 + c;
            uint32_t off = row * 256 + ((chunk ^ (row & 7)) << 4);
            *(uint4*)(smem + SM_B + off) = brow[chunk];
        }
    }
    __syncthreads();

    int mg = wid >> 1, ng = wid & 1;
    int m_off = mg * 64, n_off = ng * 64;
    int h = mg >> 1;                                 // which 128-row half
    bool skip = (bj == 2 * bi2) && (h == 1);         // lower-triangle duplicate
    bool diag = (2 * bi2 + h == bj);                 // diagonal 128x128 block

    if (!skip) {
        uint32_t acc[4][8][2];
        #pragma unroll
        for (int mt = 0; mt < 4; mt++)
            #pragma unroll
            for (int nt = 0; nt < 8; nt++) { acc[mt][nt][0] = 0u; acc[mt][nt][1] = 0u; }

        uint32_t rowA = (uint32_t)(m_off + (lane & 15));
        uint32_t rowBbase = (uint32_t)(n_off + ((lane >> 4) << 3) + (lane & 7)); // group>>1 via lane>>4
        uint32_t chA_sel = (uint32_t)(lane >> 4);        // 0/1
        uint32_t chB_sel = (uint32_t)((lane >> 3) & 1);  // 0/1

        #pragma unroll
        for (int kk = 0; kk < 8; kk++) {
            uint32_t a[4][4];
            #pragma unroll
            for (int mt = 0; mt < 4; mt++) {
                uint32_t r = rowA + mt * 16;
                uint32_t chunk = (uint32_t)(kk * 2) + chA_sel;
                uint32_t addr = sb + SM_A + r * 256 + ((chunk ^ (r & 7)) << 4);
                ldsm_x4(addr, a[mt][0], a[mt][1], a[mt][2], a[mt][3]);
            }
            uint32_t b[8][2];
            #pragma unroll
            for (int p = 0; p < 4; p++) {
                uint32_t r = rowBbase + (uint32_t)(p * 16);
                uint32_t chunk = (uint32_t)(kk * 2) + chB_sel;
                uint32_t addr = sb + SM_B + r * 256 + ((chunk ^ (r & 7)) << 4);
                ldsm_x4t(addr, b[2 * p][0], b[2 * p][1], b[2 * p + 1][0], b[2 * p + 1][1]);
            }
            #pragma unroll
            for (int mt = 0; mt < 4; mt++)
                #pragma unroll
                for (int nt = 0; nt < 8; nt++)
                    mma16816h(acc[mt][nt], a[mt][0], a[mt][1], a[mt][2], a[mt][3],
                              b[nt][0], b[nt][1]);
        }

        // ---- epilogue: ex2, row sums, col sums ----
        int lrow = lane >> 2;
        int lcol = (lane & 3) * 2;
        float colacc[8][2];
        #pragma unroll
        for (int nt = 0; nt < 8; nt++) { colacc[nt][0] = 0.0f; colacc[nt][1] = 0.0f; }

        #pragma unroll
        for (int mt = 0; mt < 4; mt++) {
            float s0 = 0.0f, s1 = 0.0f;
            int grow0 = i0 + m_off + mt * 16 + lrow;
            #pragma unroll
            for (int nt = 0; nt < 8; nt++) {
                int gcol = j0 + n_off + nt * 8 + lcol;
                float2 f0 = __half22float2(*(__half2*)&acc[mt][nt][0]); // row grow0
                float2 f1 = __half22float2(*(__half2*)&acc[mt][nt][1]); // row grow0+8
                float e0 = ex2f(f0.x), e1 = ex2f(f0.y);
                float e2 = ex2f(f1.x), e3 = ex2f(f1.y);
                if (diag) {
                    if (gcol     == grow0)     e0 = 0.0f;
                    if (gcol + 1 == grow0)     e1 = 0.0f;
                    if (gcol     == grow0 + 8) e2 = 0.0f;
                    if (gcol + 1 == grow0 + 8) e3 = 0.0f;
                }
                s0 += e0 + e1;
                s1 += e2 + e3;
                colacc[nt][0] += e0 + e2;
                colacc[nt][1] += e1 + e3;
            }
            s0 += __shfl_xor_sync(0xffffffffu, s0, 1);
            s0 += __shfl_xor_sync(0xffffffffu, s0, 2);
            s1 += __shfl_xor_sync(0xffffffffu, s1, 1);
            s1 += __shfl_xor_sync(0xffffffffu, s1, 2);
            if ((lane & 3) == 0) {
                atomicAdd(&red[m_off + mt * 16 + lrow], s0);
                atomicAdd(&red[m_off + mt * 16 + lrow + 8], s1);
            }
        }

        if (!diag) {
            #pragma unroll
            for (int nt = 0; nt < 8; nt++) {
                #pragma unroll
                for (int hh = 0; hh < 2; hh++) {
                    float c = colacc[nt][hh];
                    c += __shfl_xor_sync(0xffffffffu, c, 4);
                    c += __shfl_xor_sync(0xffffffffu, c, 8);
                    c += __shfl_xor_sync(0xffffffffu, c, 16);
                    if (lane < 4)
                        atomicAdd(&redc[n_off + nt * 8 + (lane & 3) * 2 + hh], c);
                }
            }
        }
    }

    __syncthreads();
    atomicAdd(&g_denom[i0 + tid], red[tid]);
    if (tid < 128 && bj != 2 * bi2)
        atomicAdd(&g_denom[j0 + tid], redc[tid]);
}

// ---------------- K4: per-row loss + per-class reduce + fused final ---------
__global__ void k_loss(const int* __restrict__ l32, float* __restrict__ out) {
    int i = blockIdx.x * 256 + threadIdx.x;
    int t = threadIdx.x;
    int c = (get_label(l32, i) == 0) ? 0 : 1;
    const float* Mc = g_M[c];
    float pos = 0.0f;
    #pragma unroll 16
    for (int d = 0; d < DDIM; d++)
        pos += g_eT[d * NROWS + i] * Mc[d];
    pos -= 1.0f;
    float cntm1 = (float)(g_cnt[c] - 1);
    float li = -(pos - cntm1 * logf(g_denom[i]));

    __shared__ float sh0[256], sh1[256];
    sh0[t] = (c == 0) ? li : 0.0f;
    sh1[t] = (c == 0) ? 0.0f : li;
    __syncthreads();
    for (int st = 128; st; st >>= 1) {
        if (t < st) { sh0[t] += sh0[t + st]; sh1[t] += sh1[t + st]; }
        __syncthreads();
    }
    __shared__ int ticket;
    if (t == 0) {
        atomicAdd(&g_acc[0], sh0[0]);
        atomicAdd(&g_acc[1], sh1[0]);
        __threadfence();
        ticket = atomicAdd(&g_done, 1);
    }
    __syncthreads();
    if (t == 0 && ticket == gridDim.x - 1) {
        out[0] = g_acc[0] / (float)g_cnt[0] + g_acc[1];
    }
}

// ---------------- launch -----------------------------------------------------
extern "C" void kernel_launch(void* const* d_in, const int* in_sizes, int n_in,
                              void* d_out, int out_size) {
    const float* emb = (const float*)d_in[0];
    const int*   l32 = (const int*)d_in[1];
    float*       out = (float*)d_out;

    cudaFuncSetAttribute(k_sim, cudaFuncAttributeMaxDynamicSharedMemorySize, SM_TOT);

    k_init<<<33, 256>>>(l32);
    k_normalize<<<(NROWS * 32) / 256, 256>>>(emb);
    k_classsum<<<DDIM, 256>>>(l32);
    dim3 grid(64, 32);                 // bj, bi2; invalid CTAs exit immediately
    k_sim<<<grid, 256, SM_TOT>>>();
    k_loss<<<NROWS / 256, 256>>>(l32, out);
}